// round 13
// baseline (speedup 1.0000x reference)
#include <cuda_runtime.h>
#include <cuda_bf16.h>
#include <math.h>
#include <stdint.h>

// Problem constants
#define BATCH 2
#define SEQ 4096
#define DMODEL 512
#define NHEADS 8
#define HD 64
#define WINDOW 256
#define MROWS (BATCH * SEQ)       // 8192
#define QKV_N (3 * DMODEL)        // 1536

// Pre-split bf16x2-packed buffers (u32 = 2 bf16 along the K/feature dim)
__device__ uint32_t g_xh[MROWS * DMODEL / 2],  g_xl[MROWS * DMODEL / 2];
__device__ uint32_t g_wh[QKV_N * DMODEL / 2],  g_wl[QKV_N * DMODEL / 2];
__device__ uint32_t g_owh[DMODEL * DMODEL / 2], g_owl[DMODEL * DMODEL / 2];
__device__ uint32_t g_qkvh[MROWS * QKV_N / 2], g_qkvl[MROWS * QKV_N / 2];
__device__ uint32_t g_ah[MROWS * DMODEL / 2],  g_al[MROWS * DMODEL / 2];

// ---------------------------------------------------------------------------
// Helpers
// ---------------------------------------------------------------------------
__device__ __forceinline__ void f4_to_bf16x2(float4 v,
                                             uint32_t& h0, uint32_t& h1,
                                             uint32_t& l0, uint32_t& l1)
{
    __nv_bfloat16 hx = __float2bfloat16(v.x), hy = __float2bfloat16(v.y);
    __nv_bfloat16 hz = __float2bfloat16(v.z), hw = __float2bfloat16(v.w);
    __nv_bfloat16 lx = __float2bfloat16(v.x - __bfloat162float(hx));
    __nv_bfloat16 ly = __float2bfloat16(v.y - __bfloat162float(hy));
    __nv_bfloat16 lz = __float2bfloat16(v.z - __bfloat162float(hz));
    __nv_bfloat16 lw = __float2bfloat16(v.w - __bfloat162float(hw));
    __nv_bfloat162 H0 = __halves2bfloat162(hx, hy);
    __nv_bfloat162 H1 = __halves2bfloat162(hz, hw);
    __nv_bfloat162 L0 = __halves2bfloat162(lx, ly);
    __nv_bfloat162 L1 = __halves2bfloat162(lz, lw);
    h0 = *reinterpret_cast<uint32_t*>(&H0);
    h1 = *reinterpret_cast<uint32_t*>(&H1);
    l0 = *reinterpret_cast<uint32_t*>(&L0);
    l1 = *reinterpret_cast<uint32_t*>(&L1);
}

__device__ __forceinline__ void split_pack2(float x, float y, uint32_t& hi, uint32_t& lo) {
    __nv_bfloat16 hx = __float2bfloat16(x), hy = __float2bfloat16(y);
    __nv_bfloat16 lx = __float2bfloat16(x - __bfloat162float(hx));
    __nv_bfloat16 ly = __float2bfloat16(y - __bfloat162float(hy));
    __nv_bfloat162 H = __halves2bfloat162(hx, hy);
    __nv_bfloat162 L = __halves2bfloat162(lx, ly);
    hi = *reinterpret_cast<uint32_t*>(&H);
    lo = *reinterpret_cast<uint32_t*>(&L);
}

__device__ __forceinline__ void mma_bf16(float c[4], const uint32_t a[4], const uint32_t b[2]) {
    asm volatile(
        "mma.sync.aligned.m16n8k16.row.col.f32.bf16.bf16.f32 "
        "{%0,%1,%2,%3}, {%4,%5,%6,%7}, {%8,%9}, {%0,%1,%2,%3};"
        : "+f"(c[0]), "+f"(c[1]), "+f"(c[2]), "+f"(c[3])
        : "r"(a[0]), "r"(a[1]), "r"(a[2]), "r"(a[3]),
          "r"(b[0]), "r"(b[1]));
}

__device__ __forceinline__ void ldsm_x4(uint32_t r[4], const uint32_t* p) {
    uint32_t addr = (uint32_t)__cvta_generic_to_shared(p);
    asm volatile("ldmatrix.sync.aligned.m8n8.x4.shared.b16 {%0,%1,%2,%3}, [%4];"
                 : "=r"(r[0]), "=r"(r[1]), "=r"(r[2]), "=r"(r[3]) : "r"(addr));
}

__device__ __forceinline__ void ldsm_x4_t(uint32_t r[4], const uint32_t* p) {
    uint32_t addr = (uint32_t)__cvta_generic_to_shared(p);
    asm volatile("ldmatrix.sync.aligned.m8n8.x4.trans.shared.b16 {%0,%1,%2,%3}, [%4];"
                 : "=r"(r[0]), "=r"(r[1]), "=r"(r[2]), "=r"(r[3]) : "r"(addr));
}

// ---------------------------------------------------------------------------
// Pre-split: fp32 -> (hi, lo) bf16x2 packed u32 arrays
// ---------------------------------------------------------------------------
__global__ void split_fp32_kernel(const float* __restrict__ src,
                                  uint32_t* __restrict__ dh,
                                  uint32_t* __restrict__ dl, int n4)
{
    int idx = blockIdx.x * blockDim.x + threadIdx.x;
    if (idx < n4) {
        float4 v = ((const float4*)src)[idx];
        uint32_t h0, h1, l0, l1;
        f4_to_bf16x2(v, h0, h1, l0, l1);
        ((uint2*)dh)[idx] = make_uint2(h0, h1);
        ((uint2*)dl)[idx] = make_uint2(l0, l1);
    }
}

// ---------------------------------------------------------------------------
// Pre-split bf16 tensor-core NT GEMM with bias:
//   C[M,N] = (Ah+Al)[M,K] @ (Bh+Bl)[N,K]^T + bias[N]   (3-mma scheme)
// 512 threads = 16 warps (4m x 4n), warp tile 32x32 -> 4 warps/SMSP for
// latency hiding. Block tile 128x128x32, 2-stage SMEM double buffer,
// register prefetch, ldmatrix.x4 fragments.
// SMEM rows stride 20 u32 (both STS.128 phases and LDSM phases hit all
// 32 banks exactly once). If SPLIT_OUT: writes hi/lo bf16x2; else fp32.
// ---------------------------------------------------------------------------
#define BM 128
#define BN 128
#define BK 32
#define PSTR 20

#define GEMM_SMEM_BYTES (2 * 4 * BM * PSTR * 4)   // 81920 B

template<bool SPLIT_OUT>
__global__ __launch_bounds__(512)
void gemm_bf16pre(const uint32_t* __restrict__ Agh, const uint32_t* __restrict__ Agl,
                  const uint32_t* __restrict__ Bgh, const uint32_t* __restrict__ Bgl,
                  const float* __restrict__ bias,
                  float* __restrict__ Cf,
                  uint32_t* __restrict__ Ch, uint32_t* __restrict__ Cl,
                  int M, int N, int K)
{
    extern __shared__ uint32_t smem_u32[];
    typedef uint32_t Tile[BM][PSTR];
    Tile* Ah = (Tile*)smem_u32;   // [2 stages]
    Tile* Al = Ah + 2;
    Tile* Bh = Al + 2;
    Tile* Bl = Bh + 2;

    const int tid  = threadIdx.x;
    const int warp = tid >> 5;
    const int lane = tid & 31;
    const int wm   = warp & 3;    // 4 m-warps (32 rows each)
    const int wn   = warp >> 2;   // 4 n-warps (32 cols each)
    const int m0   = blockIdx.y * BM;
    const int n0   = blockIdx.x * BN;

    const int a_row = (lane & 7) + ((lane >> 3) & 1) * 8;
    const int a_col = (lane >> 4) * 4;
    const int b_row = (lane & 7) + ((lane >> 4) & 1) * 8;
    const int b_col = ((lane >> 3) & 1) * 4;

    // loader: 1 uint4 per thread per tile per slab
    // lanes within a warp span 32 consecutive rows -> STS.128 phases cover
    // all 32 banks exactly once (20r mod 32 cycles {0,20,8,28,16,4,24,12})
    const int lrow = tid & 127;        // 0..127
    const int lq   = tid >> 7;         // 0..3 -> u32 col offset lq*4
    const int K2   = K >> 1;

    const uint32_t* agh = Agh + (size_t)(m0 + lrow) * K2 + lq * 4;
    const uint32_t* agl = Agl + (size_t)(m0 + lrow) * K2 + lq * 4;
    const uint32_t* bgh = Bgh + (size_t)(n0 + lrow) * K2 + lq * 4;
    const uint32_t* bgl = Bgl + (size_t)(n0 + lrow) * K2 + lq * 4;

    float c[2][4][4];
#pragma unroll
    for (int i = 0; i < 2; i++)
#pragma unroll
        for (int j = 0; j < 4; j++)
#pragma unroll
            for (int r = 0; r < 4; r++) c[i][j][r] = 0.0f;

    const int nslabs = K / BK;   // 16 u32 per row per slab

    // prefetch slab 0
    uint4 pah = *(const uint4*)agh;
    uint4 pal = *(const uint4*)agl;
    uint4 pbh = *(const uint4*)bgh;
    uint4 pbl = *(const uint4*)bgl;

    for (int s = 0; s < nslabs; s++) {
        const int st = s & 1;

        __syncthreads();   // previous stage fully consumed
        *(uint4*)&Ah[st][lrow][lq * 4] = pah;
        *(uint4*)&Al[st][lrow][lq * 4] = pal;
        *(uint4*)&Bh[st][lrow][lq * 4] = pbh;
        *(uint4*)&Bl[st][lrow][lq * 4] = pbl;
        __syncthreads();

        // prefetch next slab (overlaps compute below)
        if (s + 1 < nslabs) {
            const int ko = (s + 1) * 16;
            pah = *(const uint4*)(agh + ko);
            pal = *(const uint4*)(agl + ko);
            pbh = *(const uint4*)(bgh + ko);
            pbl = *(const uint4*)(bgl + ko);
        }

#pragma unroll
        for (int step = 0; step < 2; step++) {
            const int cb = step * 8;

            uint32_t ah[2][4], al[2][4];
#pragma unroll
            for (int ma = 0; ma < 2; ma++) {
                const int r0 = wm * 32 + ma * 16 + a_row;
                ldsm_x4(ah[ma], &Ah[st][r0][cb + a_col]);
                ldsm_x4(al[ma], &Al[st][r0][cb + a_col]);
            }
            uint32_t bhf[4][2], blf[4][2];
#pragma unroll
            for (int pa = 0; pa < 2; pa++) {
                const int rn = wn * 32 + pa * 16 + b_row;
                uint32_t t4[4];
                ldsm_x4(t4, &Bh[st][rn][cb + b_col]);
                bhf[2*pa][0]   = t4[0]; bhf[2*pa][1]   = t4[1];
                bhf[2*pa+1][0] = t4[2]; bhf[2*pa+1][1] = t4[3];
                ldsm_x4(t4, &Bl[st][rn][cb + b_col]);
                blf[2*pa][0]   = t4[0]; blf[2*pa][1]   = t4[1];
                blf[2*pa+1][0] = t4[2]; blf[2*pa+1][1] = t4[3];
            }
#pragma unroll
            for (int ma = 0; ma < 2; ma++)
#pragma unroll
                for (int na = 0; na < 4; na++) {
                    mma_bf16(c[ma][na], ah[ma], bhf[na]);
                    mma_bf16(c[ma][na], al[ma], bhf[na]);
                    mma_bf16(c[ma][na], ah[ma], blf[na]);
                }
        }
    }

    // epilogue: bias + stores
    const int g = lane >> 2;
    const int t = lane & 3;
    const int N2 = N >> 1;
#pragma unroll
    for (int ma = 0; ma < 2; ma++) {
        const int row = m0 + wm * 32 + ma * 16 + g;
#pragma unroll
        for (int na = 0; na < 4; na++) {
            const int col = n0 + wn * 32 + na * 8 + t * 2;
            float2 bv = *(const float2*)&bias[col];
            if (SPLIT_OUT) {
                uint32_t hi, lo;
                split_pack2(c[ma][na][0] + bv.x, c[ma][na][1] + bv.y, hi, lo);
                Ch[(size_t)row * N2 + (col >> 1)] = hi;
                Cl[(size_t)row * N2 + (col >> 1)] = lo;
                split_pack2(c[ma][na][2] + bv.x, c[ma][na][3] + bv.y, hi, lo);
                Ch[(size_t)(row + 8) * N2 + (col >> 1)] = hi;
                Cl[(size_t)(row + 8) * N2 + (col >> 1)] = lo;
            } else {
                float2 r0, r1;
                r0.x = c[ma][na][0] + bv.x; r0.y = c[ma][na][1] + bv.y;
                r1.x = c[ma][na][2] + bv.x; r1.y = c[ma][na][3] + bv.y;
                *(float2*)&Cf[(size_t)row * N + col]       = r0;
                *(float2*)&Cf[(size_t)(row + 8) * N + col] = r1;
            }
        }
    }
}

// ---------------------------------------------------------------------------
// Tensor-core sliding-window flash attention on pre-split bf16 qkv
// (known-good from R9/R11): 128 threads = 4 warps; 64 queries of one (b, h).
// ---------------------------------------------------------------------------
#define AQT 64
#define AKT 32
#define ASTR 36
#define QKV_U32 (QKV_N / 2)   // 768
#define DM_U32  (DMODEL / 2)  // 256

__global__ __launch_bounds__(128)
void attn_mma_kernel(const uint32_t* __restrict__ qkvh,
                     const uint32_t* __restrict__ qkvl,
                     uint32_t* __restrict__ ah_g,
                     uint32_t* __restrict__ al_g)
{
    __shared__ uint32_t Qh[AQT][ASTR], Ql[AQT][ASTR];
    __shared__ uint32_t Kh[AKT][ASTR], Kl[AKT][ASTR];
    __shared__ uint32_t Vh[AKT][ASTR], Vl[AKT][ASTR];

    const int b     = blockIdx.z;
    const int h     = blockIdx.y;
    const int qbase = blockIdx.x * AQT;
    const int tid   = threadIdx.x;
    const int warp  = tid >> 5;
    const int lane  = tid & 31;
    const int g     = lane >> 2;
    const int t     = lane & 3;

    const int a_row = (lane & 7) + ((lane >> 3) & 1) * 8;
    const int a_col = (lane >> 4) * 4;
    const int b_row = (lane & 7) + ((lane >> 4) & 1) * 8;
    const int b_col = ((lane >> 3) & 1) * 4;
    const int v_row = (lane & 7) + ((lane >> 3) & 1) * 8;
    const int v_col = ((lane >> 4) & 1) * 4;

    // ---- load Q tile (pure copy) ----
    {
        const int r    = tid >> 1;
        const int half = tid & 1;
        const size_t src = (size_t)(b * SEQ + qbase + r) * QKV_U32 + h * 32 + half * 16;
#pragma unroll
        for (int i = 0; i < 4; i++) {
            *(uint4*)&Qh[r][half * 16 + i * 4] = *(const uint4*)(qkvh + src + i * 4);
            *(uint4*)&Ql[r][half * 16 + i * 4] = *(const uint4*)(qkvl + src + i * 4);
        }
    }
    __syncthreads();

    uint32_t qfh[4][4], qfl[4][4];
#pragma unroll
    for (int s = 0; s < 4; s++) {
        ldsm_x4(qfh[s], &Qh[warp * 16 + a_row][s * 8 + a_col]);
        ldsm_x4(qfl[s], &Ql[warp * 16 + a_row][s * 8 + a_col]);
    }

    float o[8][4];
#pragma unroll
    for (int i = 0; i < 8; i++)
#pragma unroll
        for (int j = 0; j < 4; j++) o[i][j] = 0.0f;
    float m0 = -1e28f, m1 = -1e28f, l0 = 0.0f, l1 = 0.0f;

    const int q0 = qbase + warp * 16 + g;
    const int q1 = q0 + 8;

    int jstart = qbase - WINDOW;
    if (jstart < 0) jstart = 0;
    const int jend = qbase + AQT;

    for (int j0 = jstart; j0 < jend; j0 += AKT) {
        __syncthreads();
        // ---- load K/V tile (pure copy) ----
        {
            const int kr  = tid >> 2;
            const int qt4 = tid & 3;
            const size_t base = (size_t)(b * SEQ + j0 + kr) * QKV_U32 + h * 32 + qt4 * 8;
            *(uint4*)&Kh[kr][qt4 * 8]     = *(const uint4*)(qkvh + base + 256);
            *(uint4*)&Kh[kr][qt4 * 8 + 4] = *(const uint4*)(qkvh + base + 260);
            *(uint4*)&Kl[kr][qt4 * 8]     = *(const uint4*)(qkvl + base + 256);
            *(uint4*)&Kl[kr][qt4 * 8 + 4] = *(const uint4*)(qkvl + base + 260);
            *(uint4*)&Vh[kr][qt4 * 8]     = *(const uint4*)(qkvh + base + 512);
            *(uint4*)&Vh[kr][qt4 * 8 + 4] = *(const uint4*)(qkvh + base + 516);
            *(uint4*)&Vl[kr][qt4 * 8]     = *(const uint4*)(qkvl + base + 512);
            *(uint4*)&Vl[kr][qt4 * 8 + 4] = *(const uint4*)(qkvl + base + 516);
        }
        __syncthreads();

        // ---- S = Q K^T ----
        float sc[4][4];
#pragma unroll
        for (int na = 0; na < 4; na++)
#pragma unroll
            for (int e = 0; e < 4; e++) sc[na][e] = 0.0f;

#pragma unroll
        for (int s = 0; s < 4; s++) {
            uint32_t kh[4][2], kl[4][2], t4[4];
            ldsm_x4(t4, &Kh[b_row][s * 8 + b_col]);
            kh[0][0] = t4[0]; kh[0][1] = t4[1]; kh[1][0] = t4[2]; kh[1][1] = t4[3];
            ldsm_x4(t4, &Kh[16 + b_row][s * 8 + b_col]);
            kh[2][0] = t4[0]; kh[2][1] = t4[1]; kh[3][0] = t4[2]; kh[3][1] = t4[3];
            ldsm_x4(t4, &Kl[b_row][s * 8 + b_col]);
            kl[0][0] = t4[0]; kl[0][1] = t4[1]; kl[1][0] = t4[2]; kl[1][1] = t4[3];
            ldsm_x4(t4, &Kl[16 + b_row][s * 8 + b_col]);
            kl[2][0] = t4[0]; kl[2][1] = t4[1]; kl[3][0] = t4[2]; kl[3][1] = t4[3];
#pragma unroll
            for (int na = 0; na < 4; na++) {
                mma_bf16(sc[na], qfh[s], kh[na]);
                mma_bf16(sc[na], qfl[s], kh[na]);
                mma_bf16(sc[na], qfh[s], kl[na]);
            }
        }

#pragma unroll
        for (int na = 0; na < 4; na++) {
            sc[na][0] *= 0.125f; sc[na][1] *= 0.125f;
            sc[na][2] *= 0.125f; sc[na][3] *= 0.125f;
        }

        const bool nomask = (j0 >= qbase - 192) && (j0 <= qbase - 32);
        if (!nomask) {
#pragma unroll
            for (int na = 0; na < 4; na++) {
                const int c0 = j0 + 8 * na + 2 * t;
                const int c1 = c0 + 1;
                if (c0 > q0 || c0 < q0 - WINDOW) sc[na][0] = -1e30f;
                if (c1 > q0 || c1 < q0 - WINDOW) sc[na][1] = -1e30f;
                if (c0 > q1 || c0 < q1 - WINDOW) sc[na][2] = -1e30f;
                if (c1 > q1 || c1 < q1 - WINDOW) sc[na][3] = -1e30f;
            }
        }

        float mx0 = sc[0][0], mx1 = sc[0][2];
#pragma unroll
        for (int na = 0; na < 4; na++) {
            mx0 = fmaxf(mx0, fmaxf(sc[na][0], sc[na][1]));
            mx1 = fmaxf(mx1, fmaxf(sc[na][2], sc[na][3]));
        }
        mx0 = fmaxf(mx0, __shfl_xor_sync(0xffffffffu, mx0, 1));
        mx0 = fmaxf(mx0, __shfl_xor_sync(0xffffffffu, mx0, 2));
        mx1 = fmaxf(mx1, __shfl_xor_sync(0xffffffffu, mx1, 1));
        mx1 = fmaxf(mx1, __shfl_xor_sync(0xffffffffu, mx1, 2));

        const float mn0 = fmaxf(m0, mx0);
        const float mn1 = fmaxf(m1, mx1);
        const float al0 = __expf(m0 - mn0);
        const float al1 = __expf(m1 - mn1);
        m0 = mn0; m1 = mn1;

        float pv[4][4];
        float s0 = 0.0f, s1 = 0.0f;
#pragma unroll
        for (int na = 0; na < 4; na++) {
            pv[na][0] = __expf(sc[na][0] - mn0);
            pv[na][1] = __expf(sc[na][1] - mn0);
            pv[na][2] = __expf(sc[na][2] - mn1);
            pv[na][3] = __expf(sc[na][3] - mn1);
            s0 += pv[na][0] + pv[na][1];
            s1 += pv[na][2] + pv[na][3];
        }
        s0 += __shfl_xor_sync(0xffffffffu, s0, 1);
        s0 += __shfl_xor_sync(0xffffffffu, s0, 2);
        s1 += __shfl_xor_sync(0xffffffffu, s1, 1);
        s1 += __shfl_xor_sync(0xffffffffu, s1, 2);
        l0 = l0 * al0 + s0;
        l1 = l1 * al1 + s1;

#pragma unroll
        for (int nd = 0; nd < 8; nd++) {
            o[nd][0] *= al0; o[nd][1] *= al0;
            o[nd][2] *= al1; o[nd][3] *= al1;
        }

        uint32_t pah[2][4], pal[2][4];
#pragma unroll
        for (int s2 = 0; s2 < 2; s2++) {
            split_pack2(pv[2*s2][0],   pv[2*s2][1],   pah[s2][0], pal[s2][0]);
            split_pack2(pv[2*s2][2],   pv[2*s2][3],   pah[s2][1], pal[s2][1]);
            split_pack2(pv[2*s2+1][0], pv[2*s2+1][1], pah[s2][2], pal[s2][2]);
            split_pack2(pv[2*s2+1][2], pv[2*s2+1][3], pah[s2][3], pal[s2][3]);
        }

#pragma unroll
        for (int s2 = 0; s2 < 2; s2++) {
            uint32_t vbh[8][2], vbl[8][2], t4[4];
#pragma unroll
            for (int db = 0; db < 4; db++) {
                ldsm_x4_t(t4, &Vh[s2 * 16 + v_row][db * 8 + v_col]);
                vbh[2*db][0]   = t4[0]; vbh[2*db][1]   = t4[1];
                vbh[2*db+1][0] = t4[2]; vbh[2*db+1][1] = t4[3];
                ldsm_x4_t(t4, &Vl[s2 * 16 + v_row][db * 8 + v_col]);
                vbl[2*db][0]   = t4[0]; vbl[2*db][1]   = t4[1];
                vbl[2*db+1][0] = t4[2]; vbl[2*db+1][1] = t4[3];
            }
#pragma unroll
            for (int nd = 0; nd < 8; nd++) {
                mma_bf16(o[nd], pah[s2], vbh[nd]);
                mma_bf16(o[nd], pal[s2], vbh[nd]);
                mma_bf16(o[nd], pah[s2], vbl[nd]);
            }
        }
    }

    const float inv0 = 1.0f / l0;
    const float inv1 = 1.0f / l1;
    const size_t r0 = (size_t)(b * SEQ + q0) * DM_U32 + h * 32;
    const size_t r1 = (size_t)(b * SEQ + q1) * DM_U32 + h * 32;
#pragma unroll
    for (int nd = 0; nd < 8; nd++) {
        uint32_t hi, lo;
        split_pack2(o[nd][0] * inv0, o[nd][1] * inv0, hi, lo);
        ah_g[r0 + 4 * nd + t] = hi;
        al_g[r0 + 4 * nd + t] = lo;
        split_pack2(o[nd][2] * inv1, o[nd][3] * inv1, hi, lo);
        ah_g[r1 + 4 * nd + t] = hi;
        al_g[r1 + 4 * nd + t] = lo;
    }
}

// ---------------------------------------------------------------------------
// kernel_launch
// ---------------------------------------------------------------------------
extern "C" void kernel_launch(void* const* d_in, const int* in_sizes, int n_in,
                              void* d_out, int out_size)
{
    const float* x     = (const float*)d_in[0];
    const float* qkv_w = (const float*)d_in[1];
    const float* qkv_b = (const float*)d_in[2];
    const float* out_w = (const float*)d_in[3];
    const float* out_b = (const float*)d_in[4];
    float* out = (float*)d_out;

    uint32_t *xh, *xl, *wh, *wl, *owh, *owl, *qh, *ql, *ah, *al;
    cudaGetSymbolAddress((void**)&xh,  g_xh);   cudaGetSymbolAddress((void**)&xl,  g_xl);
    cudaGetSymbolAddress((void**)&wh,  g_wh);   cudaGetSymbolAddress((void**)&wl,  g_wl);
    cudaGetSymbolAddress((void**)&owh, g_owh);  cudaGetSymbolAddress((void**)&owl, g_owl);
    cudaGetSymbolAddress((void**)&qh,  g_qkvh); cudaGetSymbolAddress((void**)&ql,  g_qkvl);
    cudaGetSymbolAddress((void**)&ah,  g_ah);   cudaGetSymbolAddress((void**)&al,  g_al);

    cudaFuncSetAttribute(gemm_bf16pre<true>,
                         cudaFuncAttributeMaxDynamicSharedMemorySize, GEMM_SMEM_BYTES);
    cudaFuncSetAttribute(gemm_bf16pre<false>,
                         cudaFuncAttributeMaxDynamicSharedMemorySize, GEMM_SMEM_BYTES);

    // 0) pre-split inputs to bf16 hi/lo
    {
        int n4x = MROWS * DMODEL / 4;
        split_fp32_kernel<<<(n4x + 255) / 256, 256>>>(x, xh, xl, n4x);
        int n4w = QKV_N * DMODEL / 4;
        split_fp32_kernel<<<(n4w + 255) / 256, 256>>>(qkv_w, wh, wl, n4w);
        int n4o = DMODEL * DMODEL / 4;
        split_fp32_kernel<<<(n4o + 255) / 256, 256>>>(out_w, owh, owl, n4o);
    }

    // 1) QKV projection -> split bf16 qkv
    {
        dim3 grid(QKV_N / BN, MROWS / BM);
        gemm_bf16pre<true><<<grid, 512, GEMM_SMEM_BYTES>>>(
            xh, xl, wh, wl, qkv_b, nullptr, qh, ql, MROWS, QKV_N, DMODEL);
    }

    // 2) Sliding-window attention -> split bf16 attn output
    {
        dim3 grid(SEQ / AQT, NHEADS, BATCH);
        attn_mma_kernel<<<grid, 128>>>(qh, ql, ah, al);
    }

    // 3) Output projection -> fp32 final output
    {
        dim3 grid(DMODEL / BN, MROWS / BM);
        gemm_bf16pre<false><<<grid, 512, GEMM_SMEM_BYTES>>>(
            ah, al, owh, owl, out_b, out, nullptr, nullptr, MROWS, DMODEL, DMODEL);
    }
}

// round 15
// speedup vs baseline: 1.3548x; 1.3548x over previous
#include <cuda_runtime.h>
#include <cuda_bf16.h>
#include <math.h>
#include <stdint.h>

// Problem constants
#define BATCH 2
#define SEQ 4096
#define DMODEL 512
#define NHEADS 8
#define HD 64
#define WINDOW 256
#define MROWS (BATCH * SEQ)       // 8192
#define QKV_N (3 * DMODEL)        // 1536

// Pre-split bf16x2-packed buffers (u32 = 2 bf16 along the K/feature dim)
__device__ uint32_t g_xh[MROWS * DMODEL / 2],  g_xl[MROWS * DMODEL / 2];
__device__ uint32_t g_wh[QKV_N * DMODEL / 2],  g_wl[QKV_N * DMODEL / 2];
__device__ uint32_t g_owh[DMODEL * DMODEL / 2], g_owl[DMODEL * DMODEL / 2];
__device__ uint32_t g_qkvh[MROWS * QKV_N / 2], g_qkvl[MROWS * QKV_N / 2];
__device__ uint32_t g_ah[MROWS * DMODEL / 2],  g_al[MROWS * DMODEL / 2];

// ---------------------------------------------------------------------------
// Helpers
// ---------------------------------------------------------------------------
__device__ __forceinline__ void f4_to_bf16x2(float4 v,
                                             uint32_t& h0, uint32_t& h1,
                                             uint32_t& l0, uint32_t& l1)
{
    __nv_bfloat16 hx = __float2bfloat16(v.x), hy = __float2bfloat16(v.y);
    __nv_bfloat16 hz = __float2bfloat16(v.z), hw = __float2bfloat16(v.w);
    __nv_bfloat16 lx = __float2bfloat16(v.x - __bfloat162float(hx));
    __nv_bfloat16 ly = __float2bfloat16(v.y - __bfloat162float(hy));
    __nv_bfloat16 lz = __float2bfloat16(v.z - __bfloat162float(hz));
    __nv_bfloat16 lw = __float2bfloat16(v.w - __bfloat162float(hw));
    __nv_bfloat162 H0 = __halves2bfloat162(hx, hy);
    __nv_bfloat162 H1 = __halves2bfloat162(hz, hw);
    __nv_bfloat162 L0 = __halves2bfloat162(lx, ly);
    __nv_bfloat162 L1 = __halves2bfloat162(lz, lw);
    h0 = *reinterpret_cast<uint32_t*>(&H0);
    h1 = *reinterpret_cast<uint32_t*>(&H1);
    l0 = *reinterpret_cast<uint32_t*>(&L0);
    l1 = *reinterpret_cast<uint32_t*>(&L1);
}

__device__ __forceinline__ void split_pack2(float x, float y, uint32_t& hi, uint32_t& lo) {
    __nv_bfloat16 hx = __float2bfloat16(x), hy = __float2bfloat16(y);
    __nv_bfloat16 lx = __float2bfloat16(x - __bfloat162float(hx));
    __nv_bfloat16 ly = __float2bfloat16(y - __bfloat162float(hy));
    __nv_bfloat162 H = __halves2bfloat162(hx, hy);
    __nv_bfloat162 L = __halves2bfloat162(lx, ly);
    hi = *reinterpret_cast<uint32_t*>(&H);
    lo = *reinterpret_cast<uint32_t*>(&L);
}

__device__ __forceinline__ void mma_bf16(float c[4], const uint32_t a[4], const uint32_t b[2]) {
    asm volatile(
        "mma.sync.aligned.m16n8k16.row.col.f32.bf16.bf16.f32 "
        "{%0,%1,%2,%3}, {%4,%5,%6,%7}, {%8,%9}, {%0,%1,%2,%3};"
        : "+f"(c[0]), "+f"(c[1]), "+f"(c[2]), "+f"(c[3])
        : "r"(a[0]), "r"(a[1]), "r"(a[2]), "r"(a[3]),
          "r"(b[0]), "r"(b[1]));
}

__device__ __forceinline__ void ldsm_x4(uint32_t r[4], const uint32_t* p) {
    uint32_t addr = (uint32_t)__cvta_generic_to_shared(p);
    asm volatile("ldmatrix.sync.aligned.m8n8.x4.shared.b16 {%0,%1,%2,%3}, [%4];"
                 : "=r"(r[0]), "=r"(r[1]), "=r"(r[2]), "=r"(r[3]) : "r"(addr));
}

__device__ __forceinline__ void ldsm_x4_t(uint32_t r[4], const uint32_t* p) {
    uint32_t addr = (uint32_t)__cvta_generic_to_shared(p);
    asm volatile("ldmatrix.sync.aligned.m8n8.x4.trans.shared.b16 {%0,%1,%2,%3}, [%4];"
                 : "=r"(r[0]), "=r"(r[1]), "=r"(r[2]), "=r"(r[3]) : "r"(addr));
}

// ---------------------------------------------------------------------------
// Pre-split: fp32 -> (hi, lo) bf16x2 packed u32 arrays
// ---------------------------------------------------------------------------
__global__ void split_fp32_kernel(const float* __restrict__ src,
                                  uint32_t* __restrict__ dh,
                                  uint32_t* __restrict__ dl, int n4)
{
    int idx = blockIdx.x * blockDim.x + threadIdx.x;
    if (idx < n4) {
        float4 v = ((const float4*)src)[idx];
        uint32_t h0, h1, l0, l1;
        f4_to_bf16x2(v, h0, h1, l0, l1);
        ((uint2*)dh)[idx] = make_uint2(h0, h1);
        ((uint2*)dl)[idx] = make_uint2(l0, l1);
    }
}

// ---------------------------------------------------------------------------
// Pre-split bf16 tensor-core NT GEMM with bias:
//   C[M,N] = (Ah+Al)[M,K] @ (Bh+Bl)[N,K]^T + bias[N]   (3-mma scheme)
// Block tile 128x256x32, 256 threads = 8 warps (2m x 4n), warp tile 64x64
// -> 16 LDSM per 96 MMA per k16-step (ratio 6:1 vs 4:1 in R8) to relieve
// the shared pipe. Loader FIXED vs R13: each thread writes a full 8-u32
// row-half (two uint4); B's 256 rows covered by a second pass at row+128.
// 2-stage SMEM double buffer, register prefetch, PSTR=20 conflict-free.
// If SPLIT_OUT: writes hi/lo bf16x2; else fp32.
// ---------------------------------------------------------------------------
#define BM 128
#define BN 256
#define BK 32
#define PSTR 20

// stage = Ah,Al (128 rows) + Bh,Bl (256 rows), PSTR u32 each
#define STAGE_U32 ((2 * BM + 2 * BN) * PSTR)              // 15360
#define GEMM_SMEM_BYTES (2 * STAGE_U32 * 4)               // 122880 B

template<bool SPLIT_OUT>
__global__ __launch_bounds__(256)
void gemm_bf16pre(const uint32_t* __restrict__ Agh, const uint32_t* __restrict__ Agl,
                  const uint32_t* __restrict__ Bgh, const uint32_t* __restrict__ Bgl,
                  const float* __restrict__ bias,
                  float* __restrict__ Cf,
                  uint32_t* __restrict__ Ch, uint32_t* __restrict__ Cl,
                  int M, int N, int K)
{
    extern __shared__ uint32_t smem_u32[];

    const int tid  = threadIdx.x;
    const int warp = tid >> 5;
    const int lane = tid & 31;
    const int wm   = warp & 1;    // 2 m-warps (64 rows each)
    const int wn   = warp >> 1;   // 4 n-warps (64 cols each)
    const int m0   = blockIdx.y * BM;
    const int n0   = blockIdx.x * BN;

    const int a_row = (lane & 7) + ((lane >> 3) & 1) * 8;
    const int a_col = (lane >> 4) * 4;
    const int b_row = (lane & 7) + ((lane >> 4) & 1) * 8;
    const int b_col = ((lane >> 3) & 1) * 4;

    // loader: each thread owns one 8-u32 row-half (two uint4) per tile pass
    const int lrow  = tid >> 1;        // 0..127
    const int lhalf = tid & 1;         // 0/1 -> u32 col offset 0/8
    const int K2    = K >> 1;

    const uint32_t* agh  = Agh + (size_t)(m0 + lrow) * K2 + lhalf * 8;
    const uint32_t* agl  = Agl + (size_t)(m0 + lrow) * K2 + lhalf * 8;
    const uint32_t* bgh0 = Bgh + (size_t)(n0 + lrow) * K2 + lhalf * 8;
    const uint32_t* bgl0 = Bgl + (size_t)(n0 + lrow) * K2 + lhalf * 8;
    const uint32_t* bgh1 = Bgh + (size_t)(n0 + 128 + lrow) * K2 + lhalf * 8;
    const uint32_t* bgl1 = Bgl + (size_t)(n0 + 128 + lrow) * K2 + lhalf * 8;

    float c[4][8][4];
#pragma unroll
    for (int i = 0; i < 4; i++)
#pragma unroll
        for (int j = 0; j < 8; j++)
#pragma unroll
            for (int r = 0; r < 4; r++) c[i][j][r] = 0.0f;

    const int nslabs = K / BK;   // 16 u32 per row per slab

    // prefetch slab 0 (12 uint4)
    uint4 pah0 = *(const uint4*)agh,        pah1 = *(const uint4*)(agh + 4);
    uint4 pal0 = *(const uint4*)agl,        pal1 = *(const uint4*)(agl + 4);
    uint4 pb00 = *(const uint4*)bgh0,       pb01 = *(const uint4*)(bgh0 + 4);
    uint4 pb10 = *(const uint4*)bgl0,       pb11 = *(const uint4*)(bgl0 + 4);
    uint4 pb20 = *(const uint4*)bgh1,       pb21 = *(const uint4*)(bgh1 + 4);
    uint4 pb30 = *(const uint4*)bgl1,       pb31 = *(const uint4*)(bgl1 + 4);

    for (int s = 0; s < nslabs; s++) {
        const int st = s & 1;
        uint32_t* stage = smem_u32 + st * STAGE_U32;
        uint32_t (*Ah)[PSTR] = (uint32_t(*)[PSTR])stage;
        uint32_t (*Al)[PSTR] = Ah + BM;
        uint32_t (*Bh)[PSTR] = Al + BM;
        uint32_t (*Bl)[PSTR] = Bh + BN;

        __syncthreads();   // previous stage fully consumed
        *(uint4*)&Ah[lrow][lhalf * 8]           = pah0;
        *(uint4*)&Ah[lrow][lhalf * 8 + 4]       = pah1;
        *(uint4*)&Al[lrow][lhalf * 8]           = pal0;
        *(uint4*)&Al[lrow][lhalf * 8 + 4]       = pal1;
        *(uint4*)&Bh[lrow][lhalf * 8]           = pb00;
        *(uint4*)&Bh[lrow][lhalf * 8 + 4]       = pb01;
        *(uint4*)&Bl[lrow][lhalf * 8]           = pb10;
        *(uint4*)&Bl[lrow][lhalf * 8 + 4]       = pb11;
        *(uint4*)&Bh[128 + lrow][lhalf * 8]     = pb20;
        *(uint4*)&Bh[128 + lrow][lhalf * 8 + 4] = pb21;
        *(uint4*)&Bl[128 + lrow][lhalf * 8]     = pb30;
        *(uint4*)&Bl[128 + lrow][lhalf * 8 + 4] = pb31;
        __syncthreads();

        // prefetch next slab (overlaps compute below)
        if (s + 1 < nslabs) {
            const int ko = (s + 1) * 16;
            pah0 = *(const uint4*)(agh + ko);   pah1 = *(const uint4*)(agh + ko + 4);
            pal0 = *(const uint4*)(agl + ko);   pal1 = *(const uint4*)(agl + ko + 4);
            pb00 = *(const uint4*)(bgh0 + ko);  pb01 = *(const uint4*)(bgh0 + ko + 4);
            pb10 = *(const uint4*)(bgl0 + ko);  pb11 = *(const uint4*)(bgl0 + ko + 4);
            pb20 = *(const uint4*)(bgh1 + ko);  pb21 = *(const uint4*)(bgh1 + ko + 4);
            pb30 = *(const uint4*)(bgl1 + ko);  pb31 = *(const uint4*)(bgl1 + ko + 4);
        }

#pragma unroll
        for (int step = 0; step < 2; step++) {
            const int cb = step * 8;

            uint32_t bhf[8][2], blf[8][2];
#pragma unroll
            for (int pa = 0; pa < 4; pa++) {
                const int rn = wn * 64 + pa * 16 + b_row;
                uint32_t t4[4];
                ldsm_x4(t4, &Bh[rn][cb + b_col]);
                bhf[2*pa][0]   = t4[0]; bhf[2*pa][1]   = t4[1];
                bhf[2*pa+1][0] = t4[2]; bhf[2*pa+1][1] = t4[3];
                ldsm_x4(t4, &Bl[rn][cb + b_col]);
                blf[2*pa][0]   = t4[0]; blf[2*pa][1]   = t4[1];
                blf[2*pa+1][0] = t4[2]; blf[2*pa+1][1] = t4[3];
            }
#pragma unroll
            for (int ma = 0; ma < 4; ma++) {
                const int r0 = wm * 64 + ma * 16 + a_row;
                uint32_t ah[4], al[4];
                ldsm_x4(ah, &Ah[r0][cb + a_col]);
                ldsm_x4(al, &Al[r0][cb + a_col]);
#pragma unroll
                for (int na = 0; na < 8; na++) {
                    mma_bf16(c[ma][na], ah, bhf[na]);
                    mma_bf16(c[ma][na], al, bhf[na]);
                    mma_bf16(c[ma][na], ah, blf[na]);
                }
            }
        }
    }

    // epilogue: bias + stores
    const int g = lane >> 2;
    const int t = lane & 3;
    const int N2 = N >> 1;
#pragma unroll
    for (int ma = 0; ma < 4; ma++) {
        const int row = m0 + wm * 64 + ma * 16 + g;
#pragma unroll
        for (int na = 0; na < 8; na++) {
            const int col = n0 + wn * 64 + na * 8 + t * 2;
            float2 bv = *(const float2*)&bias[col];
            if (SPLIT_OUT) {
                uint32_t hi, lo;
                split_pack2(c[ma][na][0] + bv.x, c[ma][na][1] + bv.y, hi, lo);
                Ch[(size_t)row * N2 + (col >> 1)] = hi;
                Cl[(size_t)row * N2 + (col >> 1)] = lo;
                split_pack2(c[ma][na][2] + bv.x, c[ma][na][3] + bv.y, hi, lo);
                Ch[(size_t)(row + 8) * N2 + (col >> 1)] = hi;
                Cl[(size_t)(row + 8) * N2 + (col >> 1)] = lo;
            } else {
                float2 r0, r1;
                r0.x = c[ma][na][0] + bv.x; r0.y = c[ma][na][1] + bv.y;
                r1.x = c[ma][na][2] + bv.x; r1.y = c[ma][na][3] + bv.y;
                *(float2*)&Cf[(size_t)row * N + col]       = r0;
                *(float2*)&Cf[(size_t)(row + 8) * N + col] = r1;
            }
        }
    }
}

// ---------------------------------------------------------------------------
// Tensor-core sliding-window flash attention on pre-split bf16 qkv
// (known-good from R9/R11): 128 threads = 4 warps; 64 queries of one (b, h).
// ---------------------------------------------------------------------------
#define AQT 64
#define AKT 32
#define ASTR 36
#define QKV_U32 (QKV_N / 2)   // 768
#define DM_U32  (DMODEL / 2)  // 256

__global__ __launch_bounds__(128)
void attn_mma_kernel(const uint32_t* __restrict__ qkvh,
                     const uint32_t* __restrict__ qkvl,
                     uint32_t* __restrict__ ah_g,
                     uint32_t* __restrict__ al_g)
{
    __shared__ uint32_t Qh[AQT][ASTR], Ql[AQT][ASTR];
    __shared__ uint32_t Kh[AKT][ASTR], Kl[AKT][ASTR];
    __shared__ uint32_t Vh[AKT][ASTR], Vl[AKT][ASTR];

    const int b     = blockIdx.z;
    const int h     = blockIdx.y;
    const int qbase = blockIdx.x * AQT;
    const int tid   = threadIdx.x;
    const int warp  = tid >> 5;
    const int lane  = tid & 31;
    const int g     = lane >> 2;
    const int t     = lane & 3;

    const int a_row = (lane & 7) + ((lane >> 3) & 1) * 8;
    const int a_col = (lane >> 4) * 4;
    const int b_row = (lane & 7) + ((lane >> 4) & 1) * 8;
    const int b_col = ((lane >> 3) & 1) * 4;
    const int v_row = (lane & 7) + ((lane >> 3) & 1) * 8;
    const int v_col = ((lane >> 4) & 1) * 4;

    // ---- load Q tile (pure copy) ----
    {
        const int r    = tid >> 1;
        const int half = tid & 1;
        const size_t src = (size_t)(b * SEQ + qbase + r) * QKV_U32 + h * 32 + half * 16;
#pragma unroll
        for (int i = 0; i < 4; i++) {
            *(uint4*)&Qh[r][half * 16 + i * 4] = *(const uint4*)(qkvh + src + i * 4);
            *(uint4*)&Ql[r][half * 16 + i * 4] = *(const uint4*)(qkvl + src + i * 4);
        }
    }
    __syncthreads();

    uint32_t qfh[4][4], qfl[4][4];
#pragma unroll
    for (int s = 0; s < 4; s++) {
        ldsm_x4(qfh[s], &Qh[warp * 16 + a_row][s * 8 + a_col]);
        ldsm_x4(qfl[s], &Ql[warp * 16 + a_row][s * 8 + a_col]);
    }

    float o[8][4];
#pragma unroll
    for (int i = 0; i < 8; i++)
#pragma unroll
        for (int j = 0; j < 4; j++) o[i][j] = 0.0f;
    float m0 = -1e28f, m1 = -1e28f, l0 = 0.0f, l1 = 0.0f;

    const int q0 = qbase + warp * 16 + g;
    const int q1 = q0 + 8;

    int jstart = qbase - WINDOW;
    if (jstart < 0) jstart = 0;
    const int jend = qbase + AQT;

    for (int j0 = jstart; j0 < jend; j0 += AKT) {
        __syncthreads();
        // ---- load K/V tile (pure copy) ----
        {
            const int kr  = tid >> 2;
            const int qt4 = tid & 3;
            const size_t base = (size_t)(b * SEQ + j0 + kr) * QKV_U32 + h * 32 + qt4 * 8;
            *(uint4*)&Kh[kr][qt4 * 8]     = *(const uint4*)(qkvh + base + 256);
            *(uint4*)&Kh[kr][qt4 * 8 + 4] = *(const uint4*)(qkvh + base + 260);
            *(uint4*)&Kl[kr][qt4 * 8]     = *(const uint4*)(qkvl + base + 256);
            *(uint4*)&Kl[kr][qt4 * 8 + 4] = *(const uint4*)(qkvl + base + 260);
            *(uint4*)&Vh[kr][qt4 * 8]     = *(const uint4*)(qkvh + base + 512);
            *(uint4*)&Vh[kr][qt4 * 8 + 4] = *(const uint4*)(qkvh + base + 516);
            *(uint4*)&Vl[kr][qt4 * 8]     = *(const uint4*)(qkvl + base + 512);
            *(uint4*)&Vl[kr][qt4 * 8 + 4] = *(const uint4*)(qkvl + base + 516);
        }
        __syncthreads();

        // ---- S = Q K^T ----
        float sc[4][4];
#pragma unroll
        for (int na = 0; na < 4; na++)
#pragma unroll
            for (int e = 0; e < 4; e++) sc[na][e] = 0.0f;

#pragma unroll
        for (int s = 0; s < 4; s++) {
            uint32_t kh[4][2], kl[4][2], t4[4];
            ldsm_x4(t4, &Kh[b_row][s * 8 + b_col]);
            kh[0][0] = t4[0]; kh[0][1] = t4[1]; kh[1][0] = t4[2]; kh[1][1] = t4[3];
            ldsm_x4(t4, &Kh[16 + b_row][s * 8 + b_col]);
            kh[2][0] = t4[0]; kh[2][1] = t4[1]; kh[3][0] = t4[2]; kh[3][1] = t4[3];
            ldsm_x4(t4, &Kl[b_row][s * 8 + b_col]);
            kl[0][0] = t4[0]; kl[0][1] = t4[1]; kl[1][0] = t4[2]; kl[1][1] = t4[3];
            ldsm_x4(t4, &Kl[16 + b_row][s * 8 + b_col]);
            kl[2][0] = t4[0]; kl[2][1] = t4[1]; kl[3][0] = t4[2]; kl[3][1] = t4[3];
#pragma unroll
            for (int na = 0; na < 4; na++) {
                mma_bf16(sc[na], qfh[s], kh[na]);
                mma_bf16(sc[na], qfl[s], kh[na]);
                mma_bf16(sc[na], qfh[s], kl[na]);
            }
        }

#pragma unroll
        for (int na = 0; na < 4; na++) {
            sc[na][0] *= 0.125f; sc[na][1] *= 0.125f;
            sc[na][2] *= 0.125f; sc[na][3] *= 0.125f;
        }

        const bool nomask = (j0 >= qbase - 192) && (j0 <= qbase - 32);
        if (!nomask) {
#pragma unroll
            for (int na = 0; na < 4; na++) {
                const int c0 = j0 + 8 * na + 2 * t;
                const int c1 = c0 + 1;
                if (c0 > q0 || c0 < q0 - WINDOW) sc[na][0] = -1e30f;
                if (c1 > q0 || c1 < q0 - WINDOW) sc[na][1] = -1e30f;
                if (c0 > q1 || c0 < q1 - WINDOW) sc[na][2] = -1e30f;
                if (c1 > q1 || c1 < q1 - WINDOW) sc[na][3] = -1e30f;
            }
        }

        float mx0 = sc[0][0], mx1 = sc[0][2];
#pragma unroll
        for (int na = 0; na < 4; na++) {
            mx0 = fmaxf(mx0, fmaxf(sc[na][0], sc[na][1]));
            mx1 = fmaxf(mx1, fmaxf(sc[na][2], sc[na][3]));
        }
        mx0 = fmaxf(mx0, __shfl_xor_sync(0xffffffffu, mx0, 1));
        mx0 = fmaxf(mx0, __shfl_xor_sync(0xffffffffu, mx0, 2));
        mx1 = fmaxf(mx1, __shfl_xor_sync(0xffffffffu, mx1, 1));
        mx1 = fmaxf(mx1, __shfl_xor_sync(0xffffffffu, mx1, 2));

        const float mn0 = fmaxf(m0, mx0);
        const float mn1 = fmaxf(m1, mx1);
        const float al0 = __expf(m0 - mn0);
        const float al1 = __expf(m1 - mn1);
        m0 = mn0; m1 = mn1;

        float pv[4][4];
        float s0 = 0.0f, s1 = 0.0f;
#pragma unroll
        for (int na = 0; na < 4; na++) {
            pv[na][0] = __expf(sc[na][0] - mn0);
            pv[na][1] = __expf(sc[na][1] - mn0);
            pv[na][2] = __expf(sc[na][2] - mn1);
            pv[na][3] = __expf(sc[na][3] - mn1);
            s0 += pv[na][0] + pv[na][1];
            s1 += pv[na][2] + pv[na][3];
        }
        s0 += __shfl_xor_sync(0xffffffffu, s0, 1);
        s0 += __shfl_xor_sync(0xffffffffu, s0, 2);
        s1 += __shfl_xor_sync(0xffffffffu, s1, 1);
        s1 += __shfl_xor_sync(0xffffffffu, s1, 2);
        l0 = l0 * al0 + s0;
        l1 = l1 * al1 + s1;

#pragma unroll
        for (int nd = 0; nd < 8; nd++) {
            o[nd][0] *= al0; o[nd][1] *= al0;
            o[nd][2] *= al1; o[nd][3] *= al1;
        }

        uint32_t pah[2][4], pal[2][4];
#pragma unroll
        for (int s2 = 0; s2 < 2; s2++) {
            split_pack2(pv[2*s2][0],   pv[2*s2][1],   pah[s2][0], pal[s2][0]);
            split_pack2(pv[2*s2][2],   pv[2*s2][3],   pah[s2][1], pal[s2][1]);
            split_pack2(pv[2*s2+1][0], pv[2*s2+1][1], pah[s2][2], pal[s2][2]);
            split_pack2(pv[2*s2+1][2], pv[2*s2+1][3], pah[s2][3], pal[s2][3]);
        }

#pragma unroll
        for (int s2 = 0; s2 < 2; s2++) {
            uint32_t vbh[8][2], vbl[8][2], t4[4];
#pragma unroll
            for (int db = 0; db < 4; db++) {
                ldsm_x4_t(t4, &Vh[s2 * 16 + v_row][db * 8 + v_col]);
                vbh[2*db][0]   = t4[0]; vbh[2*db][1]   = t4[1];
                vbh[2*db+1][0] = t4[2]; vbh[2*db+1][1] = t4[3];
                ldsm_x4_t(t4, &Vl[s2 * 16 + v_row][db * 8 + v_col]);
                vbl[2*db][0]   = t4[0]; vbl[2*db][1]   = t4[1];
                vbl[2*db+1][0] = t4[2]; vbl[2*db+1][1] = t4[3];
            }
#pragma unroll
            for (int nd = 0; nd < 8; nd++) {
                mma_bf16(o[nd], pah[s2], vbh[nd]);
                mma_bf16(o[nd], pal[s2], vbh[nd]);
                mma_bf16(o[nd], pah[s2], vbl[nd]);
            }
        }
    }

    const float inv0 = 1.0f / l0;
    const float inv1 = 1.0f / l1;
    const size_t r0 = (size_t)(b * SEQ + q0) * DM_U32 + h * 32;
    const size_t r1 = (size_t)(b * SEQ + q1) * DM_U32 + h * 32;
#pragma unroll
    for (int nd = 0; nd < 8; nd++) {
        uint32_t hi, lo;
        split_pack2(o[nd][0] * inv0, o[nd][1] * inv0, hi, lo);
        ah_g[r0 + 4 * nd + t] = hi;
        al_g[r0 + 4 * nd + t] = lo;
        split_pack2(o[nd][2] * inv1, o[nd][3] * inv1, hi, lo);
        ah_g[r1 + 4 * nd + t] = hi;
        al_g[r1 + 4 * nd + t] = lo;
    }
}

// ---------------------------------------------------------------------------
// kernel_launch
// ---------------------------------------------------------------------------
extern "C" void kernel_launch(void* const* d_in, const int* in_sizes, int n_in,
                              void* d_out, int out_size)
{
    const float* x     = (const float*)d_in[0];
    const float* qkv_w = (const float*)d_in[1];
    const float* qkv_b = (const float*)d_in[2];
    const float* out_w = (const float*)d_in[3];
    const float* out_b = (const float*)d_in[4];
    float* out = (float*)d_out;

    uint32_t *xh, *xl, *wh, *wl, *owh, *owl, *qh, *ql, *ah, *al;
    cudaGetSymbolAddress((void**)&xh,  g_xh);   cudaGetSymbolAddress((void**)&xl,  g_xl);
    cudaGetSymbolAddress((void**)&wh,  g_wh);   cudaGetSymbolAddress((void**)&wl,  g_wl);
    cudaGetSymbolAddress((void**)&owh, g_owh);  cudaGetSymbolAddress((void**)&owl, g_owl);
    cudaGetSymbolAddress((void**)&qh,  g_qkvh); cudaGetSymbolAddress((void**)&ql,  g_qkvl);
    cudaGetSymbolAddress((void**)&ah,  g_ah);   cudaGetSymbolAddress((void**)&al,  g_al);

    cudaFuncSetAttribute(gemm_bf16pre<true>,
                         cudaFuncAttributeMaxDynamicSharedMemorySize, GEMM_SMEM_BYTES);
    cudaFuncSetAttribute(gemm_bf16pre<false>,
                         cudaFuncAttributeMaxDynamicSharedMemorySize, GEMM_SMEM_BYTES);

    // 0) pre-split inputs to bf16 hi/lo
    {
        int n4x = MROWS * DMODEL / 4;
        split_fp32_kernel<<<(n4x + 255) / 256, 256>>>(x, xh, xl, n4x);
        int n4w = QKV_N * DMODEL / 4;
        split_fp32_kernel<<<(n4w + 255) / 256, 256>>>(qkv_w, wh, wl, n4w);
        int n4o = DMODEL * DMODEL / 4;
        split_fp32_kernel<<<(n4o + 255) / 256, 256>>>(out_w, owh, owl, n4o);
    }

    // 1) QKV projection -> split bf16 qkv
    {
        dim3 grid(QKV_N / BN, MROWS / BM);
        gemm_bf16pre<true><<<grid, 256, GEMM_SMEM_BYTES>>>(
            xh, xl, wh, wl, qkv_b, nullptr, qh, ql, MROWS, QKV_N, DMODEL);
    }

    // 2) Sliding-window attention -> split bf16 attn output
    {
        dim3 grid(SEQ / AQT, NHEADS, BATCH);
        attn_mma_kernel<<<grid, 128>>>(qh, ql, ah, al);
    }

    // 3) Output projection -> fp32 final output
    {
        dim3 grid(DMODEL / BN, MROWS / BM);
        gemm_bf16pre<false><<<grid, 256, GEMM_SMEM_BYTES>>>(
            ah, al, owh, owl, out_b, out, nullptr, nullptr, MROWS, DMODEL, DMODEL);
    }
}

// round 16
// speedup vs baseline: 1.5827x; 1.1682x over previous
#include <cuda_runtime.h>
#include <cuda_fp16.h>
#include <math.h>
#include <stdint.h>

// Problem constants
#define BATCH 2
#define SEQ 4096
#define DMODEL 512
#define NHEADS 8
#define HD 64
#define WINDOW 256
#define MROWS (BATCH * SEQ)       // 8192
#define QKV_N (3 * DMODEL)        // 1536

// Pre-split fp16x2-packed buffers (u32 = 2 half along the K/feature dim)
__device__ uint32_t g_xh[MROWS * DMODEL / 2],  g_xl[MROWS * DMODEL / 2];
__device__ uint32_t g_wh[QKV_N * DMODEL / 2],  g_wl[QKV_N * DMODEL / 2];
__device__ uint32_t g_owh[DMODEL * DMODEL / 2], g_owl[DMODEL * DMODEL / 2];
__device__ uint32_t g_qkvh[MROWS * QKV_N / 2], g_qkvl[MROWS * QKV_N / 2];
__device__ uint32_t g_ah[MROWS * DMODEL / 2],  g_al[MROWS * DMODEL / 2];

// ---------------------------------------------------------------------------
// Helpers (fp16 split: a = ah + al, each fp16; a exact to ~2^-22)
// ---------------------------------------------------------------------------
__device__ __forceinline__ void f4_to_f16x2(float4 v,
                                            uint32_t& h0, uint32_t& h1,
                                            uint32_t& l0, uint32_t& l1)
{
    __half hx = __float2half(v.x), hy = __float2half(v.y);
    __half hz = __float2half(v.z), hw = __float2half(v.w);
    __half lx = __float2half(v.x - __half2float(hx));
    __half ly = __float2half(v.y - __half2float(hy));
    __half lz = __float2half(v.z - __half2float(hz));
    __half lw = __float2half(v.w - __half2float(hw));
    __half2 H0 = __halves2half2(hx, hy);
    __half2 H1 = __halves2half2(hz, hw);
    __half2 L0 = __halves2half2(lx, ly);
    __half2 L1 = __halves2half2(lz, lw);
    h0 = *reinterpret_cast<uint32_t*>(&H0);
    h1 = *reinterpret_cast<uint32_t*>(&H1);
    l0 = *reinterpret_cast<uint32_t*>(&L0);
    l1 = *reinterpret_cast<uint32_t*>(&L1);
}

__device__ __forceinline__ void split_pack2(float x, float y, uint32_t& hi, uint32_t& lo) {
    __half hx = __float2half(x), hy = __float2half(y);
    __half lx = __float2half(x - __half2float(hx));
    __half ly = __float2half(y - __half2float(hy));
    __half2 H = __halves2half2(hx, hy);
    __half2 L = __halves2half2(lx, ly);
    hi = *reinterpret_cast<uint32_t*>(&H);
    lo = *reinterpret_cast<uint32_t*>(&L);
}

__device__ __forceinline__ void mma_f16(float c[4], const uint32_t a[4], const uint32_t b[2]) {
    asm volatile(
        "mma.sync.aligned.m16n8k16.row.col.f32.f16.f16.f32 "
        "{%0,%1,%2,%3}, {%4,%5,%6,%7}, {%8,%9}, {%0,%1,%2,%3};"
        : "+f"(c[0]), "+f"(c[1]), "+f"(c[2]), "+f"(c[3])
        : "r"(a[0]), "r"(a[1]), "r"(a[2]), "r"(a[3]),
          "r"(b[0]), "r"(b[1]));
}

__device__ __forceinline__ void ldsm_x4(uint32_t r[4], const uint32_t* p) {
    uint32_t addr = (uint32_t)__cvta_generic_to_shared(p);
    asm volatile("ldmatrix.sync.aligned.m8n8.x4.shared.b16 {%0,%1,%2,%3}, [%4];"
                 : "=r"(r[0]), "=r"(r[1]), "=r"(r[2]), "=r"(r[3]) : "r"(addr));
}

__device__ __forceinline__ void ldsm_x4_t(uint32_t r[4], const uint32_t* p) {
    uint32_t addr = (uint32_t)__cvta_generic_to_shared(p);
    asm volatile("ldmatrix.sync.aligned.m8n8.x4.trans.shared.b16 {%0,%1,%2,%3}, [%4];"
                 : "=r"(r[0]), "=r"(r[1]), "=r"(r[2]), "=r"(r[3]) : "r"(addr));
}

// ---------------------------------------------------------------------------
// Pre-split: fp32 -> (hi, lo) fp16x2 packed u32 arrays
// ---------------------------------------------------------------------------
__global__ void split_fp32_kernel(const float* __restrict__ src,
                                  uint32_t* __restrict__ dh,
                                  uint32_t* __restrict__ dl, int n4)
{
    int idx = blockIdx.x * blockDim.x + threadIdx.x;
    if (idx < n4) {
        float4 v = ((const float4*)src)[idx];
        uint32_t h0, h1, l0, l1;
        f4_to_f16x2(v, h0, h1, l0, l1);
        ((uint2*)dh)[idx] = make_uint2(h0, h1);
        ((uint2*)dl)[idx] = make_uint2(l0, l1);
    }
}

// ---------------------------------------------------------------------------
// Pre-split fp16 tensor-core NT GEMM with bias (2-mma scheme):
//   C[M,N] = (Ah+Al)[M,K] @ Bh[N,K]^T + bias[N]
// Weight lo term dropped (eps ~2^-11 -> dot rel err ~2e-4, 5x under gate).
// Block tile 128x256x32, 256 threads = 8 warps (2m x 4n), warp tile 64x64.
// Per k16-step: 12 LDSM feed 64 MMA. 2-stage double buffer, PSTR=20.
// If SPLIT_OUT: writes hi/lo fp16x2; else fp32.
// ---------------------------------------------------------------------------
#define BM 128
#define BN 256
#define BK 32
#define PSTR 20

// stage = Ah,Al (128 rows each) + Bh (256 rows), PSTR u32 each
#define STAGE_U32 ((2 * BM + BN) * PSTR)                  // 10240
#define GEMM_SMEM_BYTES (2 * STAGE_U32 * 4)               // 81920 B

template<bool SPLIT_OUT>
__global__ __launch_bounds__(256)
void gemm_f16pre(const uint32_t* __restrict__ Agh, const uint32_t* __restrict__ Agl,
                 const uint32_t* __restrict__ Bgh,
                 const float* __restrict__ bias,
                 float* __restrict__ Cf,
                 uint32_t* __restrict__ Ch, uint32_t* __restrict__ Cl,
                 int M, int N, int K)
{
    extern __shared__ uint32_t smem_u32[];

    const int tid  = threadIdx.x;
    const int warp = tid >> 5;
    const int lane = tid & 31;
    const int wm   = warp & 1;    // 2 m-warps (64 rows each)
    const int wn   = warp >> 1;   // 4 n-warps (64 cols each)
    const int m0   = blockIdx.y * BM;
    const int n0   = blockIdx.x * BN;

    const int a_row = (lane & 7) + ((lane >> 3) & 1) * 8;
    const int a_col = (lane >> 4) * 4;
    const int b_row = (lane & 7) + ((lane >> 4) & 1) * 8;
    const int b_col = ((lane >> 3) & 1) * 4;

    // loader: each thread owns one 8-u32 row-half (two uint4) per tile pass
    const int lrow  = tid >> 1;        // 0..127
    const int lhalf = tid & 1;         // 0/1 -> u32 col offset 0/8
    const int K2    = K >> 1;

    const uint32_t* agh  = Agh + (size_t)(m0 + lrow) * K2 + lhalf * 8;
    const uint32_t* agl  = Agl + (size_t)(m0 + lrow) * K2 + lhalf * 8;
    const uint32_t* bgh0 = Bgh + (size_t)(n0 + lrow) * K2 + lhalf * 8;
    const uint32_t* bgh1 = Bgh + (size_t)(n0 + 128 + lrow) * K2 + lhalf * 8;

    float c[4][8][4];
#pragma unroll
    for (int i = 0; i < 4; i++)
#pragma unroll
        for (int j = 0; j < 8; j++)
#pragma unroll
            for (int r = 0; r < 4; r++) c[i][j][r] = 0.0f;

    const int nslabs = K / BK;   // 16 u32 per row per slab

    // prefetch slab 0 (8 uint4)
    uint4 pah0 = *(const uint4*)agh,   pah1 = *(const uint4*)(agh + 4);
    uint4 pal0 = *(const uint4*)agl,   pal1 = *(const uint4*)(agl + 4);
    uint4 pb00 = *(const uint4*)bgh0,  pb01 = *(const uint4*)(bgh0 + 4);
    uint4 pb10 = *(const uint4*)bgh1,  pb11 = *(const uint4*)(bgh1 + 4);

    for (int s = 0; s < nslabs; s++) {
        const int st = s & 1;
        uint32_t* stage = smem_u32 + st * STAGE_U32;
        uint32_t (*Ah)[PSTR] = (uint32_t(*)[PSTR])stage;
        uint32_t (*Al)[PSTR] = Ah + BM;
        uint32_t (*Bh)[PSTR] = Al + BM;

        __syncthreads();   // previous stage fully consumed
        *(uint4*)&Ah[lrow][lhalf * 8]           = pah0;
        *(uint4*)&Ah[lrow][lhalf * 8 + 4]       = pah1;
        *(uint4*)&Al[lrow][lhalf * 8]           = pal0;
        *(uint4*)&Al[lrow][lhalf * 8 + 4]       = pal1;
        *(uint4*)&Bh[lrow][lhalf * 8]           = pb00;
        *(uint4*)&Bh[lrow][lhalf * 8 + 4]       = pb01;
        *(uint4*)&Bh[128 + lrow][lhalf * 8]     = pb10;
        *(uint4*)&Bh[128 + lrow][lhalf * 8 + 4] = pb11;
        __syncthreads();

        // prefetch next slab (overlaps compute below)
        if (s + 1 < nslabs) {
            const int ko = (s + 1) * 16;
            pah0 = *(const uint4*)(agh + ko);   pah1 = *(const uint4*)(agh + ko + 4);
            pal0 = *(const uint4*)(agl + ko);   pal1 = *(const uint4*)(agl + ko + 4);
            pb00 = *(const uint4*)(bgh0 + ko);  pb01 = *(const uint4*)(bgh0 + ko + 4);
            pb10 = *(const uint4*)(bgh1 + ko);  pb11 = *(const uint4*)(bgh1 + ko + 4);
        }

#pragma unroll
        for (int step = 0; step < 2; step++) {
            const int cb = step * 8;

            uint32_t bhf[8][2];
#pragma unroll
            for (int pa = 0; pa < 4; pa++) {
                const int rn = wn * 64 + pa * 16 + b_row;
                uint32_t t4[4];
                ldsm_x4(t4, &Bh[rn][cb + b_col]);
                bhf[2*pa][0]   = t4[0]; bhf[2*pa][1]   = t4[1];
                bhf[2*pa+1][0] = t4[2]; bhf[2*pa+1][1] = t4[3];
            }
#pragma unroll
            for (int ma = 0; ma < 4; ma++) {
                const int r0 = wm * 64 + ma * 16 + a_row;
                uint32_t ah[4], al[4];
                ldsm_x4(ah, &Ah[r0][cb + a_col]);
                ldsm_x4(al, &Al[r0][cb + a_col]);
#pragma unroll
                for (int na = 0; na < 8; na++) {
                    mma_f16(c[ma][na], ah, bhf[na]);
                    mma_f16(c[ma][na], al, bhf[na]);
                }
            }
        }
    }

    // epilogue: bias + stores
    const int g = lane >> 2;
    const int t = lane & 3;
    const int N2 = N >> 1;
#pragma unroll
    for (int ma = 0; ma < 4; ma++) {
        const int row = m0 + wm * 64 + ma * 16 + g;
#pragma unroll
        for (int na = 0; na < 8; na++) {
            const int col = n0 + wn * 64 + na * 8 + t * 2;
            float2 bv = *(const float2*)&bias[col];
            if (SPLIT_OUT) {
                uint32_t hi, lo;
                split_pack2(c[ma][na][0] + bv.x, c[ma][na][1] + bv.y, hi, lo);
                Ch[(size_t)row * N2 + (col >> 1)] = hi;
                Cl[(size_t)row * N2 + (col >> 1)] = lo;
                split_pack2(c[ma][na][2] + bv.x, c[ma][na][3] + bv.y, hi, lo);
                Ch[(size_t)(row + 8) * N2 + (col >> 1)] = hi;
                Cl[(size_t)(row + 8) * N2 + (col >> 1)] = lo;
            } else {
                float2 r0, r1;
                r0.x = c[ma][na][0] + bv.x; r0.y = c[ma][na][1] + bv.y;
                r1.x = c[ma][na][2] + bv.x; r1.y = c[ma][na][3] + bv.y;
                *(float2*)&Cf[(size_t)row * N + col]       = r0;
                *(float2*)&Cf[(size_t)(row + 8) * N + col] = r1;
            }
        }
    }
}

// ---------------------------------------------------------------------------
// Tensor-core sliding-window flash attention on pre-split fp16 qkv.
// Structure identical to the known-good R9/R14 kernel; keeps the FULL 3-mma
// scheme (fp16: dropped term ~2^-22, error better than the bf16 version).
// 128 threads = 4 warps; 64 queries of one (b, h).
// ---------------------------------------------------------------------------
#define AQT 64
#define AKT 32
#define ASTR 36
#define QKV_U32 (QKV_N / 2)   // 768
#define DM_U32  (DMODEL / 2)  // 256

__global__ __launch_bounds__(128)
void attn_mma_kernel(const uint32_t* __restrict__ qkvh,
                     const uint32_t* __restrict__ qkvl,
                     uint32_t* __restrict__ ah_g,
                     uint32_t* __restrict__ al_g)
{
    __shared__ uint32_t Qh[AQT][ASTR], Ql[AQT][ASTR];
    __shared__ uint32_t Kh[AKT][ASTR], Kl[AKT][ASTR];
    __shared__ uint32_t Vh[AKT][ASTR], Vl[AKT][ASTR];

    const int b     = blockIdx.z;
    const int h     = blockIdx.y;
    const int qbase = blockIdx.x * AQT;
    const int tid   = threadIdx.x;
    const int warp  = tid >> 5;
    const int lane  = tid & 31;
    const int g     = lane >> 2;
    const int t     = lane & 3;

    const int a_row = (lane & 7) + ((lane >> 3) & 1) * 8;
    const int a_col = (lane >> 4) * 4;
    const int b_row = (lane & 7) + ((lane >> 4) & 1) * 8;
    const int b_col = ((lane >> 3) & 1) * 4;
    const int v_row = (lane & 7) + ((lane >> 3) & 1) * 8;
    const int v_col = ((lane >> 4) & 1) * 4;

    // ---- load Q tile (pure copy) ----
    {
        const int r    = tid >> 1;
        const int half = tid & 1;
        const size_t src = (size_t)(b * SEQ + qbase + r) * QKV_U32 + h * 32 + half * 16;
#pragma unroll
        for (int i = 0; i < 4; i++) {
            *(uint4*)&Qh[r][half * 16 + i * 4] = *(const uint4*)(qkvh + src + i * 4);
            *(uint4*)&Ql[r][half * 16 + i * 4] = *(const uint4*)(qkvl + src + i * 4);
        }
    }
    __syncthreads();

    uint32_t qfh[4][4], qfl[4][4];
#pragma unroll
    for (int s = 0; s < 4; s++) {
        ldsm_x4(qfh[s], &Qh[warp * 16 + a_row][s * 8 + a_col]);
        ldsm_x4(qfl[s], &Ql[warp * 16 + a_row][s * 8 + a_col]);
    }

    float o[8][4];
#pragma unroll
    for (int i = 0; i < 8; i++)
#pragma unroll
        for (int j = 0; j < 4; j++) o[i][j] = 0.0f;
    float m0 = -1e28f, m1 = -1e28f, l0 = 0.0f, l1 = 0.0f;

    const int q0 = qbase + warp * 16 + g;
    const int q1 = q0 + 8;

    int jstart = qbase - WINDOW;
    if (jstart < 0) jstart = 0;
    const int jend = qbase + AQT;

    for (int j0 = jstart; j0 < jend; j0 += AKT) {
        __syncthreads();
        // ---- load K/V tile (pure copy) ----
        {
            const int kr  = tid >> 2;
            const int qt4 = tid & 3;
            const size_t base = (size_t)(b * SEQ + j0 + kr) * QKV_U32 + h * 32 + qt4 * 8;
            *(uint4*)&Kh[kr][qt4 * 8]     = *(const uint4*)(qkvh + base + 256);
            *(uint4*)&Kh[kr][qt4 * 8 + 4] = *(const uint4*)(qkvh + base + 260);
            *(uint4*)&Kl[kr][qt4 * 8]     = *(const uint4*)(qkvl + base + 256);
            *(uint4*)&Kl[kr][qt4 * 8 + 4] = *(const uint4*)(qkvl + base + 260);
            *(uint4*)&Vh[kr][qt4 * 8]     = *(const uint4*)(qkvh + base + 512);
            *(uint4*)&Vh[kr][qt4 * 8 + 4] = *(const uint4*)(qkvh + base + 516);
            *(uint4*)&Vl[kr][qt4 * 8]     = *(const uint4*)(qkvl + base + 512);
            *(uint4*)&Vl[kr][qt4 * 8 + 4] = *(const uint4*)(qkvl + base + 516);
        }
        __syncthreads();

        // ---- S = Q K^T ----
        float sc[4][4];
#pragma unroll
        for (int na = 0; na < 4; na++)
#pragma unroll
            for (int e = 0; e < 4; e++) sc[na][e] = 0.0f;

#pragma unroll
        for (int s = 0; s < 4; s++) {
            uint32_t kh[4][2], kl[4][2], t4[4];
            ldsm_x4(t4, &Kh[b_row][s * 8 + b_col]);
            kh[0][0] = t4[0]; kh[0][1] = t4[1]; kh[1][0] = t4[2]; kh[1][1] = t4[3];
            ldsm_x4(t4, &Kh[16 + b_row][s * 8 + b_col]);
            kh[2][0] = t4[0]; kh[2][1] = t4[1]; kh[3][0] = t4[2]; kh[3][1] = t4[3];
            ldsm_x4(t4, &Kl[b_row][s * 8 + b_col]);
            kl[0][0] = t4[0]; kl[0][1] = t4[1]; kl[1][0] = t4[2]; kl[1][1] = t4[3];
            ldsm_x4(t4, &Kl[16 + b_row][s * 8 + b_col]);
            kl[2][0] = t4[0]; kl[2][1] = t4[1]; kl[3][0] = t4[2]; kl[3][1] = t4[3];
#pragma unroll
            for (int na = 0; na < 4; na++) {
                mma_f16(sc[na], qfh[s], kh[na]);
                mma_f16(sc[na], qfl[s], kh[na]);
                mma_f16(sc[na], qfh[s], kl[na]);
            }
        }

#pragma unroll
        for (int na = 0; na < 4; na++) {
            sc[na][0] *= 0.125f; sc[na][1] *= 0.125f;
            sc[na][2] *= 0.125f; sc[na][3] *= 0.125f;
        }

        const bool nomask = (j0 >= qbase - 192) && (j0 <= qbase - 32);
        if (!nomask) {
#pragma unroll
            for (int na = 0; na < 4; na++) {
                const int c0 = j0 + 8 * na + 2 * t;
                const int c1 = c0 + 1;
                if (c0 > q0 || c0 < q0 - WINDOW) sc[na][0] = -1e30f;
                if (c1 > q0 || c1 < q0 - WINDOW) sc[na][1] = -1e30f;
                if (c0 > q1 || c0 < q1 - WINDOW) sc[na][2] = -1e30f;
                if (c1 > q1 || c1 < q1 - WINDOW) sc[na][3] = -1e30f;
            }
        }

        float mx0 = sc[0][0], mx1 = sc[0][2];
#pragma unroll
        for (int na = 0; na < 4; na++) {
            mx0 = fmaxf(mx0, fmaxf(sc[na][0], sc[na][1]));
            mx1 = fmaxf(mx1, fmaxf(sc[na][2], sc[na][3]));
        }
        mx0 = fmaxf(mx0, __shfl_xor_sync(0xffffffffu, mx0, 1));
        mx0 = fmaxf(mx0, __shfl_xor_sync(0xffffffffu, mx0, 2));
        mx1 = fmaxf(mx1, __shfl_xor_sync(0xffffffffu, mx1, 1));
        mx1 = fmaxf(mx1, __shfl_xor_sync(0xffffffffu, mx1, 2));

        const float mn0 = fmaxf(m0, mx0);
        const float mn1 = fmaxf(m1, mx1);
        const float al0 = __expf(m0 - mn0);
        const float al1 = __expf(m1 - mn1);
        m0 = mn0; m1 = mn1;

        float pv[4][4];
        float s0 = 0.0f, s1 = 0.0f;
#pragma unroll
        for (int na = 0; na < 4; na++) {
            pv[na][0] = __expf(sc[na][0] - mn0);
            pv[na][1] = __expf(sc[na][1] - mn0);
            pv[na][2] = __expf(sc[na][2] - mn1);
            pv[na][3] = __expf(sc[na][3] - mn1);
            s0 += pv[na][0] + pv[na][1];
            s1 += pv[na][2] + pv[na][3];
        }
        s0 += __shfl_xor_sync(0xffffffffu, s0, 1);
        s0 += __shfl_xor_sync(0xffffffffu, s0, 2);
        s1 += __shfl_xor_sync(0xffffffffu, s1, 1);
        s1 += __shfl_xor_sync(0xffffffffu, s1, 2);
        l0 = l0 * al0 + s0;
        l1 = l1 * al1 + s1;

#pragma unroll
        for (int nd = 0; nd < 8; nd++) {
            o[nd][0] *= al0; o[nd][1] *= al0;
            o[nd][2] *= al1; o[nd][3] *= al1;
        }

        uint32_t pah[2][4], pal[2][4];
#pragma unroll
        for (int s2 = 0; s2 < 2; s2++) {
            split_pack2(pv[2*s2][0],   pv[2*s2][1],   pah[s2][0], pal[s2][0]);
            split_pack2(pv[2*s2][2],   pv[2*s2][3],   pah[s2][1], pal[s2][1]);
            split_pack2(pv[2*s2+1][0], pv[2*s2+1][1], pah[s2][2], pal[s2][2]);
            split_pack2(pv[2*s2+1][2], pv[2*s2+1][3], pah[s2][3], pal[s2][3]);
        }

#pragma unroll
        for (int s2 = 0; s2 < 2; s2++) {
            uint32_t vbh[8][2], vbl[8][2], t4[4];
#pragma unroll
            for (int db = 0; db < 4; db++) {
                ldsm_x4_t(t4, &Vh[s2 * 16 + v_row][db * 8 + v_col]);
                vbh[2*db][0]   = t4[0]; vbh[2*db][1]   = t4[1];
                vbh[2*db+1][0] = t4[2]; vbh[2*db+1][1] = t4[3];
                ldsm_x4_t(t4, &Vl[s2 * 16 + v_row][db * 8 + v_col]);
                vbl[2*db][0]   = t4[0]; vbl[2*db][1]   = t4[1];
                vbl[2*db+1][0] = t4[2]; vbl[2*db+1][1] = t4[3];
            }
#pragma unroll
            for (int nd = 0; nd < 8; nd++) {
                mma_f16(o[nd], pah[s2], vbh[nd]);
                mma_f16(o[nd], pal[s2], vbh[nd]);
                mma_f16(o[nd], pah[s2], vbl[nd]);
            }
        }
    }

    const float inv0 = 1.0f / l0;
    const float inv1 = 1.0f / l1;
    const size_t r0 = (size_t)(b * SEQ + q0) * DM_U32 + h * 32;
    const size_t r1 = (size_t)(b * SEQ + q1) * DM_U32 + h * 32;
#pragma unroll
    for (int nd = 0; nd < 8; nd++) {
        uint32_t hi, lo;
        split_pack2(o[nd][0] * inv0, o[nd][1] * inv0, hi, lo);
        ah_g[r0 + 4 * nd + t] = hi;
        al_g[r0 + 4 * nd + t] = lo;
        split_pack2(o[nd][2] * inv1, o[nd][3] * inv1, hi, lo);
        ah_g[r1 + 4 * nd + t] = hi;
        al_g[r1 + 4 * nd + t] = lo;
    }
}

// ---------------------------------------------------------------------------
// kernel_launch
// ---------------------------------------------------------------------------
extern "C" void kernel_launch(void* const* d_in, const int* in_sizes, int n_in,
                              void* d_out, int out_size)
{
    const float* x     = (const float*)d_in[0];
    const float* qkv_w = (const float*)d_in[1];
    const float* qkv_b = (const float*)d_in[2];
    const float* out_w = (const float*)d_in[3];
    const float* out_b = (const float*)d_in[4];
    float* out = (float*)d_out;

    uint32_t *xh, *xl, *wh, *wl, *owh, *owl, *qh, *ql, *ah, *al;
    cudaGetSymbolAddress((void**)&xh,  g_xh);   cudaGetSymbolAddress((void**)&xl,  g_xl);
    cudaGetSymbolAddress((void**)&wh,  g_wh);   cudaGetSymbolAddress((void**)&wl,  g_wl);
    cudaGetSymbolAddress((void**)&owh, g_owh);  cudaGetSymbolAddress((void**)&owl, g_owl);
    cudaGetSymbolAddress((void**)&qh,  g_qkvh); cudaGetSymbolAddress((void**)&ql,  g_qkvl);
    cudaGetSymbolAddress((void**)&ah,  g_ah);   cudaGetSymbolAddress((void**)&al,  g_al);

    cudaFuncSetAttribute(gemm_f16pre<true>,
                         cudaFuncAttributeMaxDynamicSharedMemorySize, GEMM_SMEM_BYTES);
    cudaFuncSetAttribute(gemm_f16pre<false>,
                         cudaFuncAttributeMaxDynamicSharedMemorySize, GEMM_SMEM_BYTES);

    // 0) pre-split inputs to fp16 hi/lo (weight lo arrays are written but
    //    unused by the 2-mma GEMM; kept for symmetry/fallback)
    {
        int n4x = MROWS * DMODEL / 4;
        split_fp32_kernel<<<(n4x + 255) / 256, 256>>>(x, xh, xl, n4x);
        int n4w = QKV_N * DMODEL / 4;
        split_fp32_kernel<<<(n4w + 255) / 256, 256>>>(qkv_w, wh, wl, n4w);
        int n4o = DMODEL * DMODEL / 4;
        split_fp32_kernel<<<(n4o + 255) / 256, 256>>>(out_w, owh, owl, n4o);
    }

    // 1) QKV projection -> split fp16 qkv
    {
        dim3 grid(QKV_N / BN, MROWS / BM);
        gemm_f16pre<true><<<grid, 256, GEMM_SMEM_BYTES>>>(
            xh, xl, wh, qkv_b, nullptr, qh, ql, MROWS, QKV_N, DMODEL);
    }

    // 2) Sliding-window attention -> split fp16 attn output
    {
        dim3 grid(SEQ / AQT, NHEADS, BATCH);
        attn_mma_kernel<<<grid, 128>>>(qh, ql, ah, al);
    }

    // 3) Output projection -> fp32 final output
    {
        dim3 grid(DMODEL / BN, MROWS / BM);
        gemm_f16pre<false><<<grid, 256, GEMM_SMEM_BYTES>>>(
            ah, al, owh, out_b, out, nullptr, nullptr, MROWS, DMODEL, DMODEL);
    }
}